// round 7
// baseline (speedup 1.0000x reference)
#include <cuda_runtime.h>
#include <cuda_bf16.h>
#include <cstdint>

// Problem constants
#define BB   4
#define NPTS 16384
#define SPTS 4096
#define C1   128
#define C2   256
#define CIN  384
#define H1   256
#define H2   128

#define NPB  128         // points per fused block
#define NTHR 512

// Tile row strides: k32 chunk rows = 32 bf16 + 8 pad = 40 bf16 = 80B
// (5 16B-granules, coprime 8 -> conflict-free ldmatrix)
// H1 rows = 256 bf16 + 8 pad = 264 bf16 = 528B (33 granules, coprime 8)
#define CHS  80
#define H1SB 528

// Weight chunk sizes (one k32 chunk, hi or lo plane):
//   W1: 256 rows x 80B = 20480 ; W2: 128 rows x 80B = 10240
#define W1CB 20480
#define W2CB 10240

__device__ __align__(16) unsigned char g_W1h[12 * W1CB];
__device__ __align__(16) unsigned char g_W1l[12 * W1CB];
__device__ __align__(16) unsigned char g_W2h[8 * W2CB];
__device__ __align__(16) unsigned char g_W2l[8 * W2CB];
__device__ float g_b1f[H1];
__device__ float g_b2f[H2];
__device__ int   g_ni[BB * NPTS * 3];
__device__ float g_nw[BB * NPTS * 3];

// ---------------- helpers ----------------
__device__ __forceinline__ uint32_t smem_to_u32(const void* p) {
    uint32_t a;
    asm("{ .reg .u64 t; cvta.to.shared.u64 t, %1; cvt.u32.u64 %0, t; }" : "=r"(a) : "l"(p));
    return a;
}
__device__ __forceinline__ void ldsm4(uint32_t* r, uint32_t a) {
    asm volatile("ldmatrix.sync.aligned.m8n8.x4.shared.b16 {%0,%1,%2,%3}, [%4];"
                 : "=r"(r[0]), "=r"(r[1]), "=r"(r[2]), "=r"(r[3]) : "r"(a));
}
__device__ __forceinline__ void mma_bf16(float* d, const uint32_t* a, const uint32_t* b) {
    asm volatile("mma.sync.aligned.m16n8k16.row.col.f32.bf16.bf16.f32 "
                 "{%0,%1,%2,%3}, {%4,%5,%6,%7}, {%8,%9}, {%0,%1,%2,%3};"
                 : "+f"(d[0]), "+f"(d[1]), "+f"(d[2]), "+f"(d[3])
                 : "r"(a[0]), "r"(a[1]), "r"(a[2]), "r"(a[3]), "r"(b[0]), "r"(b[1]));
}
__device__ __forceinline__ void cpa16(uint32_t dst, const void* src) {
    asm volatile("cp.async.cg.shared.global [%0], [%1], 16;" :: "r"(dst), "l"(src));
}
#define CP_COMMIT() asm volatile("cp.async.commit_group;" ::: "memory")
#define CP_WAIT0()  asm volatile("cp.async.wait_group 0;" ::: "memory")

__device__ __forceinline__ void pack_split4(const float* v, uint2& H, uint2& L) {
    unsigned int h[2], l[2];
#pragma unroll
    for (int j = 0; j < 2; j++) {
        __nv_bfloat16 h0 = __float2bfloat16(v[2 * j]);
        __nv_bfloat16 h1 = __float2bfloat16(v[2 * j + 1]);
        float l0 = v[2 * j]     - __bfloat162float(h0);
        float l1 = v[2 * j + 1] - __bfloat162float(h1);
        h[j] = (unsigned int)__bfloat16_as_ushort(h0) |
               ((unsigned int)__bfloat16_as_ushort(h1) << 16);
        l[j] = (unsigned int)__bfloat16_as_ushort(__float2bfloat16(l0)) |
               ((unsigned int)__bfloat16_as_ushort(__float2bfloat16(l1)) << 16);
    }
    H = make_uint2(h[0], h[1]);
    L = make_uint2(l[0], l[1]);
}
__device__ __forceinline__ void split2(float v0, float v1, uint32_t& hi, uint32_t& lo) {
    __nv_bfloat16 h0 = __float2bfloat16(v0), h1 = __float2bfloat16(v1);
    float l0 = v0 - __bfloat162float(h0), l1 = v1 - __bfloat162float(h1);
    hi = (uint32_t)__bfloat16_as_ushort(h0) | ((uint32_t)__bfloat16_as_ushort(h1) << 16);
    lo = (uint32_t)__bfloat16_as_ushort(__float2bfloat16(l0)) |
         ((uint32_t)__bfloat16_as_ushort(__float2bfloat16(l1)) << 16);
}

// ---------------- kernel A: fold BN, bf16-split, lay out weights (k32 chunks) --------
__global__ void prep_kernel(const float* __restrict__ W1, const float* __restrict__ b1,
                            const float* __restrict__ g1, const float* __restrict__ be1,
                            const float* __restrict__ m1, const float* __restrict__ v1,
                            const float* __restrict__ W2, const float* __restrict__ b2,
                            const float* __restrict__ g2, const float* __restrict__ be2,
                            const float* __restrict__ m2, const float* __restrict__ v2) {
    int idx = blockIdx.x * blockDim.x + threadIdx.x;
    int stride = gridDim.x * blockDim.x;

    for (int g = idx; g < 256 * 96; g += stride) {
        int o = g / 96, k0 = (g % 96) * 4;
        float a = g1[o] * rsqrtf(v1[o] + 1e-5f);
        float vv[4];
#pragma unroll
        for (int j = 0; j < 4; j++) vv[j] = W1[o * CIN + k0 + j] * a;
        uint2 H, L; pack_split4(vv, H, L);
        int chunk = k0 >> 5, kc = k0 & 31;
        size_t off = (size_t)chunk * W1CB + o * CHS + kc * 2;
        *(uint2*)(g_W1h + off) = H;
        *(uint2*)(g_W1l + off) = L;
    }
    for (int g = idx; g < 128 * 64; g += stride) {
        int o = g / 64, k0 = (g % 64) * 4;
        float a = g2[o] * rsqrtf(v2[o] + 1e-5f);
        float vv[4];
#pragma unroll
        for (int j = 0; j < 4; j++) vv[j] = W2[o * H1 + k0 + j] * a;
        uint2 H, L; pack_split4(vv, H, L);
        int chunk = k0 >> 5, kc = k0 & 31;
        size_t off = (size_t)chunk * W2CB + o * CHS + kc * 2;
        *(uint2*)(g_W2h + off) = H;
        *(uint2*)(g_W2l + off) = L;
    }
    for (int o = idx; o < H1; o += stride) {
        float a = g1[o] * rsqrtf(v1[o] + 1e-5f);
        g_b1f[o] = (b1[o] - m1[o]) * a + be1[o];
    }
    for (int o = idx; o < H2; o += stride) {
        float a = g2[o] * rsqrtf(v2[o] + 1e-5f);
        g_b2f[o] = (b2[o] - m2[o]) * a + be2[o];
    }
}

// ---------------- kernel B: exact 3-NN + interpolation weights (unchanged) ----------
__global__ void __launch_bounds__(256) nn_kernel(const float* __restrict__ xyz1,
                                                 const float* __restrict__ xyz2) {
    extern __shared__ float4 sc[];
    const int b = blockIdx.y;
    const int n = blockIdx.x * 256 + threadIdx.x;

    const float* x2 = xyz2 + b * SPTS * 3;
    for (int s = threadIdx.x; s < SPTS; s += 256) {
        float x = x2[s * 3 + 0], y = x2[s * 3 + 1], z = x2[s * 3 + 2];
        sc[s] = make_float4(fmaf(x, x, fmaf(y, y, z * z)), -2.f * x, -2.f * y, -2.f * z);
    }
    __syncthreads();

    const float* qq = xyz1 + (b * NPTS + n) * 3;
    const float qx = qq[0], qy = qq[1], qz = qq[2];

    const float INF = __int_as_float(0x7f800000);
    float d0 = INF, d1 = INF, d2 = INF;
    int i0 = 0, i1 = 0, i2 = 0;

#pragma unroll 4
    for (int s = 0; s < SPTS; s++) {
        float4 c = sc[s];
        float t = fmaf(c.y, qx, c.x);
        t = fmaf(c.z, qy, t);
        t = fmaf(c.w, qz, t);
        if (t < d2) {
            if (t < d1) {
                d2 = d1; i2 = i1;
                if (t < d0) { d1 = d0; i1 = i0; d0 = t; i0 = s; }
                else        { d1 = t;  i1 = s; }
            } else { d2 = t; i2 = s; }
        }
    }

    const float qn = fmaf(qx, qx, fmaf(qy, qy, qz * qz));
    float r0 = 1.f / ((d0 + qn) + 1e-8f);
    float r1 = 1.f / ((d1 + qn) + 1e-8f);
    float r2 = 1.f / ((d2 + qn) + 1e-8f);
    float inv = 1.f / (r0 + r1 + r2);

    const int base = (b * NPTS + n) * 3;
    g_ni[base + 0] = i0; g_ni[base + 1] = i1; g_ni[base + 2] = i2;
    g_nw[base + 0] = r0 * inv; g_nw[base + 1] = r1 * inv; g_nw[base + 2] = r2 * inv;
}

// ---------------- kernel C: pipelined fused interp + MLP via HMMA ----------------
// 128 points/block, 512 threads (16 warps), 1 block/SM, 176128 B smem.
// phase1: A1 bufs 2 x (hi 10240 | lo 10240) @0        .. 40960
//         B1 bufs 2 x (hi 20480 | lo 20480) @40960    .. 122880
// phase2: H1 hi @0 (67584) | lo @67584 (67584)        .. 135168
//         B2 bufs 2 x (hi 10240 | lo 10240) @135168   .. 176128
#define A1_OFF  0
#define A1_BUF  20480
#define A1_LO   10240
#define B1_OFF  40960
#define B1_BUF  40960
#define B1_LO   20480
#define H1H_OFF 0
#define H1L_OFF 67584
#define B2_OFF  135168
#define B2_BUF  20480
#define B2_LO   10240
#define SMEM_BYTES 176128

__global__ void __launch_bounds__(NTHR, 1) fused_kernel(const float* __restrict__ feat1,
                                                        const float* __restrict__ feat2,
                                                        float* __restrict__ out) {
    extern __shared__ __align__(128) char sm[];
    const uint32_t sb = smem_to_u32(sm);
    const int tid  = threadIdx.x;
    const int lane = tid & 31;
    const int wid  = tid >> 5;
    const int b    = blockIdx.y;
    const int n0g  = blockIdx.x * NPB;

    // producer mapping: 4 threads per point
    const int p = tid >> 2;
    const int q = tid & 3;
    const int nbase = (b * NPTS + n0g + p) * 3;
    const int j0 = g_ni[nbase], j1 = g_ni[nbase + 1], j2 = g_ni[nbase + 2];
    const float w0 = g_nw[nbase], w1 = g_nw[nbase + 1], w2 = g_nw[nbase + 2];

    // ldmatrix decomposition
    const int r8 = lane & 7;
    const int g4 = lane >> 3;
    const int gm = (g4 & 1) << 3;
    const int gk = (g4 >> 1) << 3;

    // warp tiles: GEMM1 M32xN64 (4x4 warp grid), GEMM2 M32xN32
    const int m0  = (wid >> 2) * 32;
    const int n10 = (wid & 3) * 64;
    const int n20 = (wid & 3) * 32;

    float d1[2][8][4];
#pragma unroll
    for (int mt = 0; mt < 2; mt++)
#pragma unroll
        for (int nt = 0; nt < 8; nt++)
#pragma unroll
            for (int i = 0; i < 4; i++) d1[mt][nt][i] = 0.f;

    float4 pf0, pf1, pf2;

    auto ldg_part = [&](int nc, int h) {
        const int cl = q * 8 + h * 4;
        if (nc < 4) {
            pf0 = __ldg((const float4*)(feat1 + ((size_t)(b * NPTS + n0g + p)) * C1
                                        + nc * 32 + cl));
        } else {
            const int c2 = (nc - 4) * 32 + cl;
            pf0 = __ldg((const float4*)(feat2 + ((size_t)b * SPTS + j0) * C2 + c2));
            pf1 = __ldg((const float4*)(feat2 + ((size_t)b * SPTS + j1) * C2 + c2));
            pf2 = __ldg((const float4*)(feat2 + ((size_t)b * SPTS + j2) * C2 + c2));
        }
    };
    auto sts_part = [&](int nc, int h) {
        float v[4];
        if (nc < 4) {
            v[0] = pf0.x; v[1] = pf0.y; v[2] = pf0.z; v[3] = pf0.w;
        } else {
            v[0] = fmaf(w0, pf0.x, fmaf(w1, pf1.x, w2 * pf2.x));
            v[1] = fmaf(w0, pf0.y, fmaf(w1, pf1.y, w2 * pf2.y));
            v[2] = fmaf(w0, pf0.z, fmaf(w1, pf1.z, w2 * pf2.z));
            v[3] = fmaf(w0, pf0.w, fmaf(w1, pf1.w, w2 * pf2.w));
        }
        uint2 H, L; pack_split4(v, H, L);
        char* dst = sm + A1_OFF + (nc & 1) * A1_BUF + p * CHS + (q * 8 + h * 4) * 2;
        *(uint2*)dst = H;
        *(uint2*)(dst + A1_LO) = L;
    };
    auto consume1 = [&](uint32_t Au, uint32_t Bu, int ks) {
        uint32_t ah[2][4], al[2][4];
#pragma unroll
        for (int mt = 0; mt < 2; mt++) {
            const uint32_t aad = Au + (uint32_t)((m0 + mt * 16 + r8 + gm) * CHS
                                                 + (ks * 16 + gk) * 2);
            ldsm4(ah[mt], aad);
            ldsm4(al[mt], aad + A1_LO);
        }
        uint32_t bbf[8][2];
#pragma unroll
        for (int np = 0; np < 4; np++)
            ldsm4(&bbf[2 * np][0],
                  Bu + (uint32_t)((n10 + np * 16 + r8 + gk) * CHS + (ks * 16 + gm) * 2));
#pragma unroll
        for (int mt = 0; mt < 2; mt++)
#pragma unroll
            for (int nt = 0; nt < 8; nt++) mma_bf16(d1[mt][nt], ah[mt], bbf[nt]);
#pragma unroll
        for (int mt = 0; mt < 2; mt++)
#pragma unroll
            for (int nt = 0; nt < 8; nt++) mma_bf16(d1[mt][nt], al[mt], bbf[nt]);
#pragma unroll
        for (int np = 0; np < 4; np++)
            ldsm4(&bbf[2 * np][0],
                  Bu + B1_LO + (uint32_t)((n10 + np * 16 + r8 + gk) * CHS
                                          + (ks * 16 + gm) * 2));
#pragma unroll
        for (int mt = 0; mt < 2; mt++)
#pragma unroll
            for (int nt = 0; nt < 8; nt++) mma_bf16(d1[mt][nt], ah[mt], bbf[nt]);
    };

    // ---- pre-loop: produce chunk 0 + cp.async W1 chunk 0 ----
    ldg_part(0, 0); sts_part(0, 0);
    ldg_part(0, 1); sts_part(0, 1);
    {
        const uint32_t dH = sb + B1_OFF;
        for (int i = tid * 16; i < W1CB; i += NTHR * 16) {
            cpa16(dH + i, g_W1h + i);
            cpa16(dH + B1_LO + i, g_W1l + i);
        }
        CP_COMMIT();
    }

    // ---- phase 1: 12 chunks of k32 ----
    for (int ci = 0; ci < 12; ci++) {
        const int s = ci & 1;
        const uint32_t Au = sb + A1_OFF + s * A1_BUF;
        const uint32_t Bu = sb + B1_OFF + s * B1_BUF;
        const int nc = ci + 1;

        CP_WAIT0();          // W1(ci) arrived (thread-local)
        __syncthreads();     // W1(ci)/A(ci) visible to all; consume(ci-1) done everywhere

        if (nc < 12) {       // prefetch weights for next chunk during this mma phase
            const unsigned char* srcH = g_W1h + (size_t)nc * W1CB;
            const unsigned char* srcL = g_W1l + (size_t)nc * W1CB;
            const uint32_t dH = sb + B1_OFF + (nc & 1) * B1_BUF;
            for (int i = tid * 16; i < W1CB; i += NTHR * 16) {
                cpa16(dH + i, srcH + i);
                cpa16(dH + B1_LO + i, srcL + i);
            }
            CP_COMMIT();
        }

        if (nc < 12) ldg_part(nc, 0);
        consume1(Au, Bu, 0);
        if (nc < 12) { sts_part(nc, 0); ldg_part(nc, 1); }
        consume1(Au, Bu, 1);
        if (nc < 12) sts_part(nc, 1);
    }
    __syncthreads();         // all consumes done before H1/B2 region overwrite

    // ---- prefetch W2 chunk 0, then epilogue1 (covers the cp.async) ----
    {
        const uint32_t dH = sb + B2_OFF;
        for (int i = tid * 16; i < W2CB; i += NTHR * 16) {
            cpa16(dH + i, g_W2h + i);
            cpa16(dH + B2_LO + i, g_W2l + i);
        }
        CP_COMMIT();
    }
    // epilogue1: bias + ReLU + bf16 split -> H1 smem
#pragma unroll
    for (int mt = 0; mt < 2; mt++)
#pragma unroll
        for (int nt = 0; nt < 8; nt++) {
            const int col = n10 + nt * 8 + (lane & 3) * 2;
            const float bb0 = g_b1f[col], bb1 = g_b1f[col + 1];
            const int row = m0 + mt * 16 + (lane >> 2);
            const float* dd = d1[mt][nt];
            uint32_t hi, lo;
            split2(fmaxf(dd[0] + bb0, 0.f), fmaxf(dd[1] + bb1, 0.f), hi, lo);
            *(uint32_t*)(sm + H1H_OFF + row * H1SB + col * 2) = hi;
            *(uint32_t*)(sm + H1L_OFF + row * H1SB + col * 2) = lo;
            split2(fmaxf(dd[2] + bb0, 0.f), fmaxf(dd[3] + bb1, 0.f), hi, lo);
            *(uint32_t*)(sm + H1H_OFF + (row + 8) * H1SB + col * 2) = hi;
            *(uint32_t*)(sm + H1L_OFF + (row + 8) * H1SB + col * 2) = lo;
        }

    // ---- phase 2: GEMM2, 8 chunks of k32 ----
    float d2[2][4][4];
#pragma unroll
    for (int mt = 0; mt < 2; mt++)
#pragma unroll
        for (int nt = 0; nt < 4; nt++)
#pragma unroll
            for (int i = 0; i < 4; i++) d2[mt][nt][i] = 0.f;

    for (int cj = 0; cj < 8; cj++) {
        const int s = cj & 1;
        const uint32_t Bu = sb + B2_OFF + s * B2_BUF;
        const int ncj = cj + 1;

        CP_WAIT0();          // W2(cj) arrived
        __syncthreads();     // also orders H1 writes (cj==0) and buffer reuse

        if (ncj < 8) {
            const unsigned char* srcH = g_W2h + (size_t)ncj * W2CB;
            const unsigned char* srcL = g_W2l + (size_t)ncj * W2CB;
            const uint32_t dH = sb + B2_OFF + (ncj & 1) * B2_BUF;
            for (int i = tid * 16; i < W2CB; i += NTHR * 16) {
                cpa16(dH + i, srcH + i);
                cpa16(dH + B2_LO + i, srcL + i);
            }
            CP_COMMIT();
        }

#pragma unroll
        for (int ks = 0; ks < 2; ks++) {
            uint32_t ah[2][4], al[2][4];
#pragma unroll
            for (int mt = 0; mt < 2; mt++) {
                const uint32_t aad = sb + (uint32_t)((m0 + mt * 16 + r8 + gm) * H1SB
                                                     + (cj * 32 + ks * 16 + gk) * 2);
                ldsm4(ah[mt], aad + H1H_OFF);
                ldsm4(al[mt], aad + H1L_OFF);
            }
            uint32_t bbf[4][2];
#pragma unroll
            for (int np = 0; np < 2; np++)
                ldsm4(&bbf[2 * np][0],
                      Bu + (uint32_t)((n20 + np * 16 + r8 + gk) * CHS + (ks * 16 + gm) * 2));
#pragma unroll
            for (int mt = 0; mt < 2; mt++)
#pragma unroll
                for (int nt = 0; nt < 4; nt++) mma_bf16(d2[mt][nt], ah[mt], bbf[nt]);
#pragma unroll
            for (int mt = 0; mt < 2; mt++)
#pragma unroll
                for (int nt = 0; nt < 4; nt++) mma_bf16(d2[mt][nt], al[mt], bbf[nt]);
#pragma unroll
            for (int np = 0; np < 2; np++)
                ldsm4(&bbf[2 * np][0],
                      Bu + B2_LO + (uint32_t)((n20 + np * 16 + r8 + gk) * CHS
                                              + (ks * 16 + gm) * 2));
#pragma unroll
            for (int mt = 0; mt < 2; mt++)
#pragma unroll
                for (int nt = 0; nt < 4; nt++) mma_bf16(d2[mt][nt], ah[mt], bbf[nt]);
        }
    }

    // ---- epilogue2: bias + ReLU -> fp32 out ----
#pragma unroll
    for (int mt = 0; mt < 2; mt++)
#pragma unroll
        for (int nt = 0; nt < 4; nt++) {
            const int col = n20 + nt * 8 + (lane & 3) * 2;
            const float bb0 = g_b2f[col], bb1 = g_b2f[col + 1];
            const int row = m0 + mt * 16 + (lane >> 2);
            const float* dd = d2[mt][nt];
            float2 v0 = make_float2(fmaxf(dd[0] + bb0, 0.f), fmaxf(dd[1] + bb1, 0.f));
            float2 v1 = make_float2(fmaxf(dd[2] + bb0, 0.f), fmaxf(dd[3] + bb1, 0.f));
            *(float2*)(out + ((size_t)(b * NPTS + n0g + row)) * H2 + col) = v0;
            *(float2*)(out + ((size_t)(b * NPTS + n0g + row + 8)) * H2 + col) = v1;
        }
}

// ---------------- launch ----------------
extern "C" void kernel_launch(void* const* d_in, const int* in_sizes, int n_in,
                              void* d_out, int out_size) {
    const float* xyz1  = (const float*)d_in[0];
    const float* feat1 = (const float*)d_in[1];
    const float* xyz2  = (const float*)d_in[2];
    const float* feat2 = (const float*)d_in[3];
    const float* W1  = (const float*)d_in[4];
    const float* b1  = (const float*)d_in[5];
    const float* g1  = (const float*)d_in[6];
    const float* be1 = (const float*)d_in[7];
    const float* m1  = (const float*)d_in[8];
    const float* v1  = (const float*)d_in[9];
    const float* W2  = (const float*)d_in[10];
    const float* b2  = (const float*)d_in[11];
    const float* g2  = (const float*)d_in[12];
    const float* be2 = (const float*)d_in[13];
    const float* m2  = (const float*)d_in[14];
    const float* v2  = (const float*)d_in[15];
    float* out = (float*)d_out;

    cudaFuncSetAttribute(nn_kernel, cudaFuncAttributeMaxDynamicSharedMemorySize,
                         SPTS * (int)sizeof(float4));
    cudaFuncSetAttribute(fused_kernel, cudaFuncAttributeMaxDynamicSharedMemorySize,
                         SMEM_BYTES);

    prep_kernel<<<64, 256>>>(W1, b1, g1, be1, m1, v1, W2, b2, g2, be2, m2, v2);
    nn_kernel<<<dim3(NPTS / 256, BB), 256, SPTS * sizeof(float4)>>>(xyz1, xyz2);
    fused_kernel<<<dim3(NPTS / NPB, BB), NTHR, SMEM_BYTES>>>(feat1, feat2, out);
}